// round 5
// baseline (speedup 1.0000x reference)
#include <cuda_runtime.h>
#include <math.h>

#define D   32
#define HH  64
#define BB  8192
#define TT  256
#define MT  64      // rows per CTA; 128 CTAs
// 256 threads: tx = tid&15 (16 col-blocks), ty = tid>>4 (16 row-blocks of 4)

// smem float offsets
#define O_W1D 0              // 33*128 dup'd swizzled
#define O_W2D 4224           // 64*128
#define O_W3D 12416          // 64*64
#define O_B1D 16512          // 128 dup'd
#define O_B2D 16640
#define O_B3D 16768          // 64 dup'd
#define O_STD 16832          // 32
#define O_TS  16864          // 256
#define O_Z   17120          // 32*64 rotated
#define O_H1  19168          // 64*64 rotated
#define O_H2  23264          // 64*64 rotated
#define SMEM_FLOATS 27360

typedef unsigned long long u64;

__device__ __forceinline__ u64 ffma2(u64 a, u64 b, u64 c) {
    u64 d; asm("fma.rn.f32x2 %0, %1, %2, %3;" : "=l"(d) : "l"(a), "l"(b), "l"(c)); return d;
}
__device__ __forceinline__ u64 fmul2(u64 a, u64 b) {
    u64 d; asm("mul.rn.f32x2 %0, %1, %2;" : "=l"(d) : "l"(a), "l"(b)); return d;
}
__device__ __forceinline__ u64 pk(float x, float y) {
    u64 r; asm("mov.b64 %0, {%1, %2};" : "=l"(r) : "f"(x), "f"(y)); return r;
}
__device__ __forceinline__ float2 unpk(u64 v) {
    float2 r; asm("mov.b64 {%0, %1}, %2;" : "=f"(r.x), "=f"(r.y) : "l"(v)); return r;
}
__device__ __forceinline__ float tanha(float x) {
    float y; asm("tanh.approx.f32 %0, %1;" : "=f"(y) : "f"(x)); return y;
}

union F4U { float4 f; u64 u[2]; };
__device__ __forceinline__ F4U ld4(const float* p) { F4U r; r.f = *(const float4*)p; return r; }

__global__ __launch_bounds__(256, 1)
void sde_kernel(const float* __restrict__ z0,
                const float* __restrict__ ts,
                const float* __restrict__ dW,
                const float* __restrict__ W1, const float* __restrict__ b1,
                const float* __restrict__ W2, const float* __restrict__ b2,
                const float* __restrict__ W3, const float* __restrict__ b3,
                const float* __restrict__ logstd,
                float* __restrict__ out)
{
    extern __shared__ float sm[];
    float* sW1d = sm + O_W1D;
    float* sW2d = sm + O_W2D;
    float* sW3d = sm + O_W3D;
    float* sb1d = sm + O_B1D;
    float* sb2d = sm + O_B2D;
    float* sb3d = sm + O_B3D;
    float* sstd = sm + O_STD;
    float* sTs  = sm + O_TS;
    float* sZ   = sm + O_Z;
    float* sH1  = sm + O_H1;
    float* sH2  = sm + O_H2;

    const int tid = threadIdx.x;
    const int tx  = tid & 15;
    const int ty  = tid >> 4;
    const int m0  = ty * 4;
    const int j0  = tx * 4;
    const int d0  = tx * 2;
    const int base = blockIdx.x * MT;

    // ---- staging: weights duplicated ({w,w} adjacent), 16B-unit swizzled ----
    for (int i = tid; i < 33 * 128; i += 256) {
        int row = i >> 7, f = i & 127;
        int u = f >> 2, us = u ^ ((u >> 3) & 1);
        sW1d[(row << 7) + (us << 2) + (f & 3)] = W1[(row << 6) + (f >> 1)];
    }
    for (int i = tid; i < 64 * 128; i += 256) {
        int row = i >> 7, f = i & 127;
        int u = f >> 2, us = u ^ ((u >> 3) & 1);
        sW2d[(row << 7) + (us << 2) + (f & 3)] = W2[(row << 6) + (f >> 1)];
    }
    for (int i = tid; i < 64 * 64; i += 256) {
        int row = i >> 6, f = i & 63;
        sW3d[(row << 6) + f] = W3[(row << 5) + (f >> 1)];
    }
    if (tid < 128) { sb1d[tid] = b1[tid >> 1]; sb2d[tid] = b2[tid >> 1]; }
    if (tid < 64)  { sb3d[tid] = b3[tid >> 1]; }
    if (tid < 32)  { sstd[tid] = expf(logstd[tid]); }
    sTs[tid] = ts[tid];
    __syncthreads();

    // ---- hoisted per-thread constants & offsets ----
    const int u0 = 2 * tx, u1 = 2 * tx + 1;
    const int ob0 = (u0 ^ ((u0 >> 3) & 1)) << 2;
    const int ob1 = (u1 ^ ((u1 >> 3) & 1)) << 2;
    // rotation offsets: write side (group index = feature>>2)
    const int osH = ((ty + tx) & 15) << 2;          // sH writes, group = tx
    const int osZ = ((ty + (tx >> 1)) & 15) << 2;   // sZ writes, group = tx>>1

    u64 bc1[4], bc2[4], bc3[2], w1t[4];
    {
        F4U t;
        t = ld4(sb1d + 8 * tx);     bc1[0] = t.u[0]; bc1[1] = t.u[1];
        t = ld4(sb1d + 8 * tx + 4); bc1[2] = t.u[0]; bc1[3] = t.u[1];
        t = ld4(sb2d + 8 * tx);     bc2[0] = t.u[0]; bc2[1] = t.u[1];
        t = ld4(sb2d + 8 * tx + 4); bc2[2] = t.u[0]; bc2[3] = t.u[1];
        t = ld4(sb3d + 4 * tx);     bc3[0] = t.u[0]; bc3[1] = t.u[1];
        t = ld4(sW1d + ob0);        w1t[0] = t.u[0]; w1t[1] = t.u[1];
        t = ld4(sW1d + ob1);        w1t[2] = t.u[0]; w1t[3] = t.u[1];
    }
    const u64 s2base = pk(sstd[d0], sstd[d0 + 1]);

    // ---- z init: registers (col-packed per row), out[0], rotated sZ ----
    u64 zp[4];
    #pragma unroll
    for (int r = 0; r < 4; r++) {
        zp[r] = *(const u64*)&z0[(size_t)(base + m0 + r) * D + d0];
        *(u64*)&out[(size_t)(base + m0 + r) * D + d0] = zp[r];
    }
    #pragma unroll
    for (int c = 0; c < 2; c++) {
        float4 v;
        if (c == 0) { v.x = unpk(zp[0]).x; v.y = unpk(zp[1]).x; v.z = unpk(zp[2]).x; v.w = unpk(zp[3]).x; }
        else        { v.x = unpk(zp[0]).y; v.y = unpk(zp[1]).y; v.z = unpk(zp[2]).y; v.w = unpk(zp[3]).y; }
        *(float4*)(sZ + (d0 + c) * 64 + osZ) = v;
    }
    __syncthreads();

    // ==================== time loop ====================
    for (int t = 0; t < TT - 1; ++t) {
        const float tcur = sTs[t];
        const float dtv  = sTs[t + 1] - tcur;
        const float sq   = sqrtf(dtv);

        // prefetch noise (consumed in epilogue3)
        u64 dwv[4];
        {
            const float* dwp = dW + ((size_t)t * BB + base + m0) * D + d0;
            #pragma unroll
            for (int r = 0; r < 4; r++) dwv[r] = *(const u64*)(dwp + (size_t)r * D);
        }

        u64 acc[2][4];

        // ---------- GEMM1: [t,z] @ W1 ----------
        {
            u64 t2 = pk(tcur, tcur);
            #pragma unroll
            for (int c = 0; c < 4; c++) {
                u64 ic = ffma2(t2, w1t[c], bc1[c]);
                acc[0][c] = ic; acc[1][c] = ic;
            }
            #pragma unroll
            for (int g = 0; g < 8; ++g) {
                const int oa = ((ty + g) & 15) << 2;
                const float* arow = sZ + g * 256;
                const float* wrow = sW1d + (g * 4 + 1) * 128;
                #pragma unroll
                for (int kk = 0; kk < 4; ++kk) {
                    F4U a  = ld4(arow + kk * 64 + oa);
                    F4U b0 = ld4(wrow + kk * 128 + ob0);
                    F4U b1v = ld4(wrow + kk * 128 + ob1);
                    #pragma unroll
                    for (int c = 0; c < 4; c++) {
                        u64 bv = (c < 2) ? b0.u[c] : b1v.u[c - 2];
                        acc[0][c] = ffma2(a.u[0], bv, acc[0][c]);
                        acc[1][c] = ffma2(a.u[1], bv, acc[1][c]);
                    }
                }
            }
            #pragma unroll
            for (int c = 0; c < 4; c++) {
                float2 r0 = unpk(acc[0][c]), r1 = unpk(acc[1][c]);
                float4 v;
                v.x = tanha(r0.x); v.y = tanha(r0.y); v.z = tanha(r1.x); v.w = tanha(r1.y);
                *(float4*)(sH1 + (j0 + c) * 64 + osH) = v;
            }
        }
        __syncthreads();

        // ---------- GEMM2: h1 @ W2 ----------
        {
            #pragma unroll
            for (int c = 0; c < 4; c++) { acc[0][c] = bc2[c]; acc[1][c] = bc2[c]; }
            #pragma unroll 4
            for (int g = 0; g < 16; ++g) {
                const int oa = ((ty + g) & 15) << 2;
                const float* arow = sH1 + g * 256;
                const float* wrow = sW2d + g * 512;
                #pragma unroll
                for (int kk = 0; kk < 4; ++kk) {
                    F4U a  = ld4(arow + kk * 64 + oa);
                    F4U b0 = ld4(wrow + kk * 128 + ob0);
                    F4U b1v = ld4(wrow + kk * 128 + ob1);
                    #pragma unroll
                    for (int c = 0; c < 4; c++) {
                        u64 bv = (c < 2) ? b0.u[c] : b1v.u[c - 2];
                        acc[0][c] = ffma2(a.u[0], bv, acc[0][c]);
                        acc[1][c] = ffma2(a.u[1], bv, acc[1][c]);
                    }
                }
            }
            #pragma unroll
            for (int c = 0; c < 4; c++) {
                float2 r0 = unpk(acc[0][c]), r1 = unpk(acc[1][c]);
                float4 v;
                v.x = tanha(r0.x); v.y = tanha(r0.y); v.z = tanha(r1.x); v.w = tanha(r1.y);
                *(float4*)(sH2 + (j0 + c) * 64 + osH) = v;
            }
        }
        __syncthreads();

        // ---------- GEMM3: h2 @ W3 + Euler-Maruyama ----------
        {
            u64 a3[2][2];
            a3[0][0] = bc3[0]; a3[0][1] = bc3[1];
            a3[1][0] = bc3[0]; a3[1][1] = bc3[1];
            #pragma unroll 4
            for (int g = 0; g < 16; ++g) {
                const int oa = ((ty + g) & 15) << 2;
                const float* arow = sH2 + g * 256;
                const float* wrow = sW3d + g * 256;
                #pragma unroll
                for (int kk = 0; kk < 4; ++kk) {
                    F4U a = ld4(arow + kk * 64 + oa);
                    F4U b = ld4(wrow + kk * 64 + 4 * tx);
                    #pragma unroll
                    for (int c = 0; c < 2; c++) {
                        a3[0][c] = ffma2(a.u[0], b.u[c], a3[0][c]);
                        a3[1][c] = ffma2(a.u[1], b.u[c], a3[1][c]);
                    }
                }
            }

            const u64 dt2 = pk(dtv, dtv);
            const u64 s2  = fmul2(s2base, pk(sq, sq));
            float* orow = out + ((size_t)(t + 1) * BB + base + m0) * D + d0;
            #pragma unroll
            for (int r = 0; r < 4; r++) {
                float2 c0 = unpk(a3[r >> 1][0]);
                float2 c1 = unpk(a3[r >> 1][1]);
                u64 fe = (r & 1) ? pk(c0.y, c1.y) : pk(c0.x, c1.x);
                zp[r] = ffma2(fe, dt2, ffma2(s2, dwv[r], zp[r]));
                *(u64*)(orow + (size_t)r * D) = zp[r];
            }
            #pragma unroll
            for (int c = 0; c < 2; c++) {
                float4 v;
                if (c == 0) { v.x = unpk(zp[0]).x; v.y = unpk(zp[1]).x; v.z = unpk(zp[2]).x; v.w = unpk(zp[3]).x; }
                else        { v.x = unpk(zp[0]).y; v.y = unpk(zp[1]).y; v.z = unpk(zp[2]).y; v.w = unpk(zp[3]).y; }
                *(float4*)(sZ + (d0 + c) * 64 + osZ) = v;
            }
        }
        __syncthreads();
    }
}

extern "C" void kernel_launch(void* const* d_in, const int* in_sizes, int n_in,
                              void* d_out, int out_size)
{
    (void)in_sizes; (void)n_in; (void)out_size;
    const float* z0     = (const float*)d_in[0];
    const float* ts     = (const float*)d_in[1];
    const float* dW     = (const float*)d_in[2];
    const float* W1     = (const float*)d_in[3];
    const float* b1     = (const float*)d_in[4];
    const float* W2     = (const float*)d_in[5];
    const float* b2     = (const float*)d_in[6];
    const float* W3     = (const float*)d_in[7];
    const float* b3     = (const float*)d_in[8];
    const float* logstd = (const float*)d_in[9];
    float* out = (float*)d_out;

    static bool attr_set = false;  // idempotent attribute; not a work guard
    if (!attr_set) {
        cudaFuncSetAttribute(sde_kernel,
                             cudaFuncAttributeMaxDynamicSharedMemorySize,
                             SMEM_FLOATS * sizeof(float));
        attr_set = true;
    }

    sde_kernel<<<BB / MT, 256, SMEM_FLOATS * sizeof(float)>>>(
        z0, ts, dW, W1, b1, W2, b2, W3, b3, logstd, out);
}